// round 10
// baseline (speedup 1.0000x reference)
#include <cuda_runtime.h>
#include <cuda_bf16.h>
#include <stdint.h>

// Warp-per-row gather. Lane j: table = j>>3, sub-float4 = j&7.
// Row output = [W0[t0] | W1[t1] | W2[t2] | W3[t3]] (4 x 32 floats = 128).
//
// Index dtype (int64 vs int32) detected in-kernel: each warp inspects the
// high 32-bit halves of the first 32 words of T. int64 little-endian with
// values < 366 -> all high halves zero; int32 -> odd words are random
// indices, P(all 32 zero) ~ 1e-50. One cached load + one ballot per warp.
__global__ void __launch_bounds__(256)
time_encoder_gather_kernel(const void* __restrict__ Tv,
                           const float4* __restrict__ W0,
                           const float4* __restrict__ W1,
                           const float4* __restrict__ W2,
                           const float4* __restrict__ W3,
                           float4* __restrict__ out,
                           int N) {
    const int lane = threadIdx.x & 31;
    const int dim  = lane >> 3;   // which table (0..3)
    const int sub  = lane & 7;    // which float4 within the 32-float slice

    // --- in-warp dtype detection ---
    const unsigned int* t32 = (const unsigned int*)Tv;
    unsigned int hi = __ldg(&t32[2 * lane + 1]);
    const bool is64 = (__ballot_sync(0xFFFFFFFFu, hi != 0u) == 0u);

    // Per-lane table base pointer (loop-invariant).
    const float4* W = (dim == 0) ? W0 : (dim == 1) ? W1 : (dim == 2) ? W2 : W3;

    const int warp   = (int)((blockIdx.x * blockDim.x + threadIdx.x) >> 5);
    const int nwarps = (int)((gridDim.x * blockDim.x) >> 5);

    const int*       T32 = (const int*)Tv;
    const long long* T64 = (const long long*)Tv;

    if (is64) {
        for (int row = warp; row < N; row += nwarps) {
            int idx = (int)__ldg(&T64[(size_t)row * 4 + dim]);
            float4 v = __ldg(&W[idx * 8 + sub]);      // tables ~57KB: L1-resident
            __stcs(&out[(size_t)row * 32 + lane], v); // write-once: evict-first
        }
    } else {
        for (int row = warp; row < N; row += nwarps) {
            int idx = __ldg(&T32[(size_t)row * 4 + dim]);
            float4 v = __ldg(&W[idx * 8 + sub]);
            __stcs(&out[(size_t)row * 32 + lane], v);
        }
    }
}

extern "C" void kernel_launch(void* const* d_in, const int* in_sizes, int n_in,
                              void* d_out, int out_size) {
    const void*   T  = d_in[0];
    const float4* W0 = (const float4*)d_in[1];
    const float4* W1 = (const float4*)d_in[2];
    const float4* W2 = (const float4*)d_in[3];
    const float4* W3 = (const float4*)d_in[4];
    float4* out = (float4*)d_out;

    const int N = in_sizes[0] / 4;  // T has N*4 index elements

    // Oversubscription sweep (wall us): 1184->182.5, 4736->165.5, 7104->161.9,
    // 14208->158.4, 28416->156.4, 56832->153.7. Terminal doubling: 148 x 768.
    const int threads = 256;
    const int blocks  = 148 * 768;
    time_encoder_gather_kernel<<<blocks, threads>>>(T, W0, W1, W2, W3, out, N);
}

// round 11
// speedup vs baseline: 1.0475x; 1.0475x over previous
#include <cuda_runtime.h>
#include <cuda_bf16.h>
#include <stdint.h>

// Warp-per-row gather. Lane j: table = j>>3, sub-float4 = j&7.
// Row output = [W0[t0] | W1[t1] | W2[t2] | W3[t3]] (4 x 32 floats = 128).
//
// Index dtype (int64 vs int32) detected in-kernel: each warp inspects the
// high 32-bit halves of the first 32 words of T. int64 little-endian with
// values < 366 -> all high halves zero; int32 -> odd words are random
// indices, P(all 32 zero) ~ 1e-50. One cached load + one ballot per warp.
__global__ void __launch_bounds__(256)
time_encoder_gather_kernel(const void* __restrict__ Tv,
                           const float4* __restrict__ W0,
                           const float4* __restrict__ W1,
                           const float4* __restrict__ W2,
                           const float4* __restrict__ W3,
                           float4* __restrict__ out,
                           int N) {
    const int lane = threadIdx.x & 31;
    const int dim  = lane >> 3;   // which table (0..3)
    const int sub  = lane & 7;    // which float4 within the 32-float slice

    // --- in-warp dtype detection ---
    const unsigned int* t32 = (const unsigned int*)Tv;
    unsigned int hi = __ldg(&t32[2 * lane + 1]);
    const bool is64 = (__ballot_sync(0xFFFFFFFFu, hi != 0u) == 0u);

    // Per-lane table base pointer (loop-invariant).
    const float4* W = (dim == 0) ? W0 : (dim == 1) ? W1 : (dim == 2) ? W2 : W3;

    const int warp   = (int)((blockIdx.x * blockDim.x + threadIdx.x) >> 5);
    const int nwarps = (int)((gridDim.x * blockDim.x) >> 5);

    const int*       T32 = (const int*)Tv;
    const long long* T64 = (const long long*)Tv;

    if (is64) {
        for (int row = warp; row < N; row += nwarps) {
            int idx = (int)__ldg(&T64[(size_t)row * 4 + dim]);
            float4 v = __ldg(&W[idx * 8 + sub]);      // tables ~57KB: L1-resident
            __stcs(&out[(size_t)row * 32 + lane], v); // write-once: evict-first
        }
    } else {
        for (int row = warp; row < N; row += nwarps) {
            int idx = __ldg(&T32[(size_t)row * 4 + dim]);
            float4 v = __ldg(&W[idx * 8 + sub]);
            __stcs(&out[(size_t)row * 32 + lane], v);
        }
    }
}

extern "C" void kernel_launch(void* const* d_in, const int* in_sizes, int n_in,
                              void* d_out, int out_size) {
    const void*   T  = d_in[0];
    const float4* W0 = (const float4*)d_in[1];
    const float4* W1 = (const float4*)d_in[2];
    const float4* W2 = (const float4*)d_in[3];
    const float4* W3 = (const float4*)d_in[4];
    float4* out = (float4*)d_out;

    const int N = in_sizes[0] / 4;  // T has N*4 index elements

    // Oversubscription sweep (wall us): 1184->182.5, 4736->165.5, 7104->161.9,
    // 14208->158.4, 28416->156.4, 56832->153.7, 113664->162.3 (cliff).
    // Bracketed; probe interior point 148 x 512.
    const int threads = 256;
    const int blocks  = 148 * 512;
    time_encoder_gather_kernel<<<blocks, threads>>>(T, W0, W1, W2, W3, out, N);
}

// round 12
// speedup vs baseline: 1.0674x; 1.0189x over previous
#include <cuda_runtime.h>
#include <cuda_bf16.h>
#include <stdint.h>

// Warp-per-row gather. Lane j: table = j>>3, sub-float4 = j&7.
// Row output = [W0[t0] | W1[t1] | W2[t2] | W3[t3]] (4 x 32 floats = 128).
//
// Index dtype (int64 vs int32) detected in-kernel: each warp inspects the
// high 32-bit halves of the first 32 words of T. int64 little-endian with
// values < 366 -> all high halves zero; int32 -> odd words are random
// indices, P(all 32 zero) ~ 1e-50. One cached load + one ballot per warp.
__global__ void __launch_bounds__(512)
time_encoder_gather_kernel(const void* __restrict__ Tv,
                           const float4* __restrict__ W0,
                           const float4* __restrict__ W1,
                           const float4* __restrict__ W2,
                           const float4* __restrict__ W3,
                           float4* __restrict__ out,
                           int N) {
    const int lane = threadIdx.x & 31;
    const int dim  = lane >> 3;   // which table (0..3)
    const int sub  = lane & 7;    // which float4 within the 32-float slice

    // --- in-warp dtype detection ---
    const unsigned int* t32 = (const unsigned int*)Tv;
    unsigned int hi = __ldg(&t32[2 * lane + 1]);
    const bool is64 = (__ballot_sync(0xFFFFFFFFu, hi != 0u) == 0u);

    // Per-lane table base pointer (loop-invariant).
    const float4* W = (dim == 0) ? W0 : (dim == 1) ? W1 : (dim == 2) ? W2 : W3;

    const int warp   = (int)((blockIdx.x * blockDim.x + threadIdx.x) >> 5);
    const int nwarps = (int)((gridDim.x * blockDim.x) >> 5);

    const int*       T32 = (const int*)Tv;
    const long long* T64 = (const long long*)Tv;

    if (is64) {
        for (int row = warp; row < N; row += nwarps) {
            int idx = (int)__ldg(&T64[(size_t)row * 4 + dim]);
            float4 v = __ldg(&W[idx * 8 + sub]);      // tables ~57KB: L1-resident
            __stcs(&out[(size_t)row * 32 + lane], v); // write-once: evict-first
        }
    } else {
        for (int row = warp; row < N; row += nwarps) {
            int idx = __ldg(&T32[(size_t)row * 4 + dim]);
            float4 v = __ldg(&W[idx * 8 + sub]);
            __stcs(&out[(size_t)row * 32 + lane], v);
        }
    }
}

extern "C" void kernel_launch(void* const* d_in, const int* in_sizes, int n_in,
                              void* d_out, int out_size) {
    const void*   T  = d_in[0];
    const float4* W0 = (const float4*)d_in[1];
    const float4* W1 = (const float4*)d_in[2];
    const float4* W2 = (const float4*)d_in[3];
    const float4* W3 = (const float4*)d_in[4];
    float4* out = (float4*)d_out;

    const int N = in_sizes[0] / 4;  // T has N*4 index elements

    // Best measured warp count: 454,656 (56832 x 256thr, wall 153.7us).
    // Same warps, half the CTAs: 512-thread blocks, 28416 CTAs.
    const int threads = 512;
    const int blocks  = 148 * 192;   // 28416
    time_encoder_gather_kernel<<<blocks, threads>>>(T, W0, W1, W2, W3, out, N);
}